// round 13
// baseline (speedup 1.0000x reference)
#include <cuda_runtime.h>
#include <cstdint>

// Model_NPZD_68401649156380 — R13: R10's 4B cp.async chunk pipeline, denser.
// G=2 batches/block (104 ODEs), 4-slot ring with 3 chunks in flight,
// snapshots stored directly to gmem (no o[4][8], no transpose epilogue),
// 6 blocks/SM. idx(w,s) = 168w + 3s ; chunk c step i: col = 168w + 24c + 3i.

#define NB      2048
#define NWK     52
#define NHRS    8760
#define DT      0.125f
#define NT      256
#define G       2
#define NCOMP   (G * NWK)              // 104
#define NCH     7
#define NSLOT   4
#define IPAD    9                      // float2 per (g,w) per chunk (8 + pad)
#define SLOTF2  (NCOMP * IPAD)         // 936 float2
#define SLOTB   (SLOTF2 * 8)           // 7488 B
#define SMEM_BYTES (NSLOT * SLOTB)     // 29952 B
#define CH_ELE  (NCOMP * 8)            // 832 (f,m) pairs per chunk
#define KMAX    4                      // ceil(832/256); k=3 only tid<64

__global__ __launch_bounds__(NT, 6) void npzd_kernel(
    const float* __restrict__ X_in,     // (B, 52, 5, 1)
    const float* __restrict__ gf,       // (B, 8760)
    const float* __restrict__ gm,       // (B, 8760)
    const float* __restrict__ pv,       // (B, 10)
    float* __restrict__ out)            // (B, 52, 4, 8)
{
    extern __shared__ float2 ring[];    // [NSLOT][104][IPAD]
    const int tid = threadIdx.x;
    const int b0  = blockIdx.x * G;

    const uint32_t ringsh = (uint32_t)__cvta_generic_to_shared(ring);

    // ---- one-time per-thread load addressing ----
    int      srcOff[KMAX];   // gmem float offset for chunk 0; +24 per chunk
    uint32_t dstRel[KMAX];   // smem byte offset within a slot
    #pragma unroll
    for (int k = 0; k < KMAX; ++k) {
        int e = tid + NT * k;
        if (e < CH_ELE) {
            int gw = e >> 3;            // 0..103
            int i  = e & 7;
            int g  = gw / NWK;
            int w  = gw - g * NWK;
            srcOff[k] = (b0 + g) * NHRS + 168 * w + 3 * i;
            dstRel[k] = (uint32_t)((gw * IPAD + i) * 8);
        } else { srcOff[k] = 0; dstRel[k] = 0; }
    }

    auto issue = [&](int c, int slot) {
        const uint32_t sb  = ringsh + (uint32_t)(slot * SLOTB);
        const int      add = 24 * c;
        #pragma unroll
        for (int k = 0; k < KMAX; ++k) {
            if (k == KMAX - 1 && tid >= (CH_ELE - NT * (KMAX - 1)))
                break;
            const float* fp = gf + (srcOff[k] + add);
            const float* mp = gm + (srcOff[k] + add);
            uint32_t d = sb + dstRel[k];
            asm volatile("cp.async.ca.shared.global [%0], [%1], 4;\n"
                         :: "r"(d), "l"(fp) : "memory");
            asm volatile("cp.async.ca.shared.global [%0], [%1], 4;\n"
                         :: "r"(d + 4), "l"(mp) : "memory");
        }
        asm volatile("cp.async.commit_group;\n" ::: "memory");
    };

    // Prime: 3 chunks in flight.
    issue(0, 0);
    issue(1, 1);
    issue(2, 2);

    // ---- per-thread ODE identity / params (overlaps first gathers) ----
    const int g = tid / NWK;            // valid for tid < NCOMP
    const int w = tid - g * NWK;
    const int b = b0 + g;
    const int t = blockIdx.x * NCOMP + tid;   // global ODE index

    float chiC=0, rho2=0, gam01=0, lam005=0, eps01=0,
          alp03=0, bet06=0, eta015=0, phi04=0, zet01=0, rem=0;
    float N=0, P=0, Z=0, D=0;
    float* op = out + (size_t)t * 32;
    if (tid < NCOMP) {
        const float* p = pv + b * 10;
        chiC   = p[0];
        rho2   = p[1] * 2.0f;
        gam01  = p[2] * 0.1f;
        lam005 = p[3] * 0.05f;
        eps01  = p[4] * 0.1f;
        alp03  = p[5] * 0.3f;
        bet06  = p[6] * 0.6f;
        eta015 = p[7] * 0.15f;
        phi04  = p[8] * 0.4f;
        zet01  = p[9] * 0.1f;
        rem    = 1.0f - alp03 - bet06;

        const float* xi = X_in + ((size_t)(b * NWK + w)) * 5;
        N = xi[1]; P = xi[2]; Z = xi[3]; D = xi[4];

        // snapshot k = 0
        op[0] = N; op[8] = P; op[16] = Z; op[24] = D;
    }

    #pragma unroll 1
    for (int c = 0; c < NCH; ++c) {
        // Ensure chunk c landed; allow the younger in-flight groups to pend.
        if (c <= NCH - 3)
            asm volatile("cp.async.wait_group 2;\n" ::: "memory");
        else if (c == NCH - 2)
            asm volatile("cp.async.wait_group 1;\n" ::: "memory");
        else
            asm volatile("cp.async.wait_group 0;\n" ::: "memory");
        __syncthreads();   // chunk c visible; slot (c+3)%4 fully consumed

        if (c + 3 < NCH)
            issue(c + 3, (c + 3) & (NSLOT - 1));

        if (tid < NCOMP) {
            const float2* sp = ring + (c & (NSLOT - 1)) * SLOTF2 + tid * IPAD;
            #pragma unroll
            for (int i = 0; i < 8; ++i) {
                float2 fm = sp[i];
                float ft = fm.x, mt = fm.y;

                float Pc = fmaxf(0.01f, P);
                float Zc = fmaxf(0.01f, Z);
                float gN = N / (chiC + N);
                float zg = rho2 * (1.0f - __expf(-lam005 * Pc)) * Zc;
                float up = gN * ft * Pc;                    // Vm = 1

                float Nn = N + DT * (-up + alp03 * zg + eps01 * P + gam01 * Z
                                     + phi04 * D + mt * (8.0f - N));   // Q0=8
                float Pn = P + DT * (up - zg - eps01 * P - eta015 * P - mt * P);
                float Zn = Z + DT * (bet06 * zg - gam01 * Z - mt * Z);
                float Dn = D + DT * (eta015 * P + rem * zg - phi04 * D
                                     - zet01 * D - mt * D);
                N = Nn; P = Pn; Z = Zn; D = Dn;
            }
            // snapshot k = c+1 straight to gmem (L2-resident line)
            op[c + 1]      = N;
            op[8 + c + 1]  = P;
            op[16 + c + 1] = Z;
            op[24 + c + 1] = D;
        }
    }
}

extern "C" void kernel_launch(void* const* d_in, const int* in_sizes, int n_in,
                              void* d_out, int out_size)
{
    (void)in_sizes; (void)n_in; (void)out_size;
    const float* X_in = (const float*)d_in[0];
    const float* gf   = (const float*)d_in[1];
    const float* gm   = (const float*)d_in[2];
    const float* pvv  = (const float*)d_in[3];
    float* out        = (float*)d_out;

    cudaFuncSetAttribute(npzd_kernel,
                         cudaFuncAttributeMaxDynamicSharedMemorySize,
                         SMEM_BYTES);
    npzd_kernel<<<NB / G, NT, SMEM_BYTES>>>(X_in, gf, gm, pvv, out);
}

// round 15
// speedup vs baseline: 1.3659x; 1.3659x over previous
#include <cuda_runtime.h>
#include <cuda.h>
#include <cstdint>
#include <dlfcn.h>

// Model_NPZD_68401649156380 — R15: R14 (TMA 3D tiled loads) with
//  (1) 128B-aligned smem ring base (cp.async.bulk.tensor requirement),
//  (2) host-side checks of cuTensorMapEncodeTiled + R10-pipeline fallback.
// gf/gm viewed as (2048, 52, 168) row-major. Per block (G=2 batches) per
// chunk c (8 steps): ONE cp.async.bulk.tensor.3d per array, box (24@x=24c,
// 52, 2), into a 3-slot mbarrier ring. idx(w,s)=168w+3s; step i: col=24c+3i.

#define NB      2048
#define NWK     52
#define NHRS    8760
#define DT      0.125f
#define NT      128
#define G       2
#define NCOMP   (G * NWK)               // 104
#define NCH     7
#define NSLOT   3
#define TILEF   (G * NWK * 24)          // 2496 floats per array per chunk
#define TILEB   (TILEF * 4)             // 9984 B (multiple of 128)
#define SLOTF   (2 * TILEF)
#define SLOTB   (2 * TILEB)             // 19968 B (multiple of 128)
#define SMEM_BYTES (NSLOT * SLOTB + 128)   // +128 for alignment slack
#define GRID    (NB / G)                // 1024

__device__ __forceinline__ void mbar_wait(uint32_t mb, uint32_t parity)
{
    uint32_t done;
    asm volatile(
        "{\n\t.reg .pred p;\n\t"
        "mbarrier.try_wait.parity.acquire.cta.shared::cta.b64 p, [%1], %2;\n\t"
        "selp.b32 %0, 1, 0, p;\n\t}"
        : "=r"(done) : "r"(mb), "r"(parity) : "memory");
    if (!done) {
        asm volatile(
            "{\n\t.reg .pred P1;\n\t"
            "W_%=:\n\t"
            "mbarrier.try_wait.parity.acquire.cta.shared::cta.b64 P1, [%0], %1, 0x989680;\n\t"
            "@P1 bra.uni D_%=;\n\t"
            "bra.uni W_%=;\n\t"
            "D_%=:\n\t}"
            :: "r"(mb), "r"(parity) : "memory");
    }
}

__global__ __launch_bounds__(NT) void npzd_tma(
    const __grid_constant__ CUtensorMap tmf,
    const __grid_constant__ CUtensorMap tmm,
    const float* __restrict__ X_in,
    const float* __restrict__ pv,
    float* __restrict__ out)
{
    extern __shared__ float rraw[];
    __shared__ __align__(8) unsigned long long mbar[NSLOT];

    const int tid = threadIdx.x;
    const int b0  = blockIdx.x * G;

    // 128B-align the ring base (TMA smem destination requirement).
    uint32_t raw_sh = (uint32_t)__cvta_generic_to_shared(rraw);
    uint32_t rbase  = (raw_sh + 127u) & ~127u;
    float*   ringp  = (float*)((char*)rraw + (rbase - raw_sh));

    const uint32_t mbsh = (uint32_t)__cvta_generic_to_shared(mbar);
    const CUtensorMap* mf = &tmf;
    const CUtensorMap* mm = &tmm;

    if (tid == 0) {
        #pragma unroll
        for (int s = 0; s < NSLOT; ++s)
            asm volatile("mbarrier.init.shared.b64 [%0], 1;"
                         :: "r"(mbsh + s * 8) : "memory");
        asm volatile("fence.proxy.async.shared::cta;" ::: "memory");
    }
    __syncthreads();

    auto issue = [&](int c) {
        const int s = c % NSLOT;
        const uint32_t mb = mbsh + s * 8;
        const uint32_t df = rbase + (uint32_t)(s * SLOTB);
        const uint32_t dm = df + TILEB;
        asm volatile("mbarrier.arrive.expect_tx.shared.b64 _, [%0], %1;"
                     :: "r"(mb), "r"((uint32_t)SLOTB) : "memory");
        asm volatile(
            "cp.async.bulk.tensor.3d.shared::cta.global.tile.mbarrier::complete_tx::bytes"
            " [%0], [%1, {%2, %3, %4}], [%5];"
            :: "r"(df), "l"(mf), "r"(24 * c), "r"(0), "r"(b0), "r"(mb) : "memory");
        asm volatile(
            "cp.async.bulk.tensor.3d.shared::cta.global.tile.mbarrier::complete_tx::bytes"
            " [%0], [%1, {%2, %3, %4}], [%5];"
            :: "r"(dm), "l"(mm), "r"(24 * c), "r"(0), "r"(b0), "r"(mb) : "memory");
    };

    if (tid == 0) { issue(0); issue(1); }

    const int g = tid / NWK;
    const int w = tid - g * NWK;
    const int b = b0 + g;

    float chiC=0, rho2=0, gam01=0, lam005=0, eps01=0,
          alp03=0, bet06=0, eta015=0, phi04=0, zet01=0, rem=0;
    float N=0, P=0, Z=0, D=0;
    if (tid < NCOMP) {
        const float* p = pv + b * 10;
        chiC   = p[0];
        rho2   = p[1] * 2.0f;
        gam01  = p[2] * 0.1f;
        lam005 = p[3] * 0.05f;
        eps01  = p[4] * 0.1f;
        alp03  = p[5] * 0.3f;
        bet06  = p[6] * 0.6f;
        eta015 = p[7] * 0.15f;
        phi04  = p[8] * 0.4f;
        zet01  = p[9] * 0.1f;
        rem    = 1.0f - alp03 - bet06;

        const float* xi = X_in + ((size_t)(b * NWK + w)) * 5;
        N = xi[1]; P = xi[2]; Z = xi[3]; D = xi[4];
    }

    float o[4][8];
    o[0][0] = N; o[1][0] = P; o[2][0] = Z; o[3][0] = D;

    #pragma unroll 1
    for (int c = 0; c < NCH; ++c) {
        const int s = c % NSLOT;
        mbar_wait(mbsh + s * 8, (uint32_t)((c / NSLOT) & 1));

        if (tid < NCOMP) {
            const float* sf = ringp + s * SLOTF + (g * NWK + w) * 24;
            const float* sm = sf + TILEF;
            #pragma unroll
            for (int i = 0; i < 8; ++i) {
                float ft = sf[3 * i];
                float mt = sm[3 * i];

                float Pc = fmaxf(0.01f, P);
                float Zc = fmaxf(0.01f, Z);
                float gN = N / (chiC + N);
                float zg = rho2 * (1.0f - __expf(-lam005 * Pc)) * Zc;
                float up = gN * ft * Pc;

                float Nn = N + DT * (-up + alp03 * zg + eps01 * P + gam01 * Z
                                     + phi04 * D + mt * (8.0f - N));
                float Pn = P + DT * (up - zg - eps01 * P - eta015 * P - mt * P);
                float Zn = Z + DT * (bet06 * zg - gam01 * Z - mt * Z);
                float Dn = D + DT * (eta015 * P + rem * zg - phi04 * D
                                     - zet01 * D - mt * D);
                N = Nn; P = Pn; Z = Zn; D = Dn;
            }
            o[0][c + 1] = N; o[1][c + 1] = P; o[2][c + 1] = Z; o[3][c + 1] = D;
        }
        __syncthreads();

        if (tid == 0 && c + 2 < NCH)
            issue(c + 2);
    }
    __syncthreads();

    float* obuf = ringp;                 // 104*33 = 3432 floats, fits
    if (tid < NCOMP) {
        float* ob = obuf + tid * 33;
        #pragma unroll
        for (int cc = 0; cc < 4; ++cc)
            #pragma unroll
            for (int k = 0; k < 8; ++k)
                ob[cc * 8 + k] = o[cc][k];
    }
    __syncthreads();

    float* outb = out + (size_t)blockIdx.x * (NCOMP * 32);
    #pragma unroll
    for (int i = tid; i < NCOMP * 32; i += NT) {
        int t2 = i >> 5;
        int m  = i & 31;
        outb[i] = obuf[t2 * 33 + m];
    }
}

// ======================= Fallback: proven R10 pipeline =======================
#define FB_NT    256
#define FB_G     4
#define FB_NCOMP (FB_G * NWK)            // 208
#define FB_IPAD  9
#define FB_SLOTF2 (FB_NCOMP * FB_IPAD)   // 1872
#define FB_SLOTB  (FB_SLOTF2 * 8)
#define FB_SMEM   (3 * FB_SLOTB)         // 44928
#define FB_CHE    (FB_NCOMP * 8)         // 1664
#define FB_KMAX   7

__global__ __launch_bounds__(FB_NT, 4) void npzd_fb(
    const float* __restrict__ X_in, const float* __restrict__ gf,
    const float* __restrict__ gm, const float* __restrict__ pv,
    float* __restrict__ out)
{
    extern __shared__ float2 ring[];
    const int tid = threadIdx.x;
    const int b0  = blockIdx.x * FB_G;
    const uint32_t ringsh = (uint32_t)__cvta_generic_to_shared(ring);

    int      srcOff[FB_KMAX];
    uint32_t dstRel[FB_KMAX];
    #pragma unroll
    for (int k = 0; k < FB_KMAX; ++k) {
        int e = tid + FB_NT * k;
        if (e < FB_CHE) {
            int gw = e >> 3, i = e & 7;
            int g = gw / NWK, w = gw - g * NWK;
            srcOff[k] = (b0 + g) * NHRS + 168 * w + 3 * i;
            dstRel[k] = (uint32_t)((gw * FB_IPAD + i) * 8);
        } else { srcOff[k] = 0; dstRel[k] = 0; }
    }
    auto issue = [&](int c, int slot) {
        const uint32_t sb = ringsh + (uint32_t)(slot * FB_SLOTB);
        const int add = 24 * c;
        #pragma unroll
        for (int k = 0; k < FB_KMAX; ++k) {
            if (k == FB_KMAX - 1 && tid >= (FB_CHE - FB_NT * (FB_KMAX - 1))) break;
            uint32_t d = sb + dstRel[k];
            asm volatile("cp.async.ca.shared.global [%0], [%1], 4;\n"
                         :: "r"(d), "l"(gf + (srcOff[k] + add)) : "memory");
            asm volatile("cp.async.ca.shared.global [%0], [%1], 4;\n"
                         :: "r"(d + 4), "l"(gm + (srcOff[k] + add)) : "memory");
        }
        asm volatile("cp.async.commit_group;\n" ::: "memory");
    };
    issue(0, 0); issue(1, 1);

    const int g = tid / NWK, w = tid - g * NWK, b = b0 + g;
    float chiC=0, rho2=0, gam01=0, lam005=0, eps01=0,
          alp03=0, bet06=0, eta015=0, phi04=0, zet01=0, rem=0;
    float N=0, P=0, Z=0, D=0;
    if (tid < FB_NCOMP) {
        const float* p = pv + b * 10;
        chiC = p[0]; rho2 = p[1]*2.0f; gam01 = p[2]*0.1f; lam005 = p[3]*0.05f;
        eps01 = p[4]*0.1f; alp03 = p[5]*0.3f; bet06 = p[6]*0.6f;
        eta015 = p[7]*0.15f; phi04 = p[8]*0.4f; zet01 = p[9]*0.1f;
        rem = 1.0f - alp03 - bet06;
        const float* xi = X_in + ((size_t)(b * NWK + w)) * 5;
        N = xi[1]; P = xi[2]; Z = xi[3]; D = xi[4];
    }
    float o[4][8];
    o[0][0]=N; o[1][0]=P; o[2][0]=Z; o[3][0]=D;
    #pragma unroll 1
    for (int c = 0; c < NCH; ++c) {
        if (c == NCH - 1) asm volatile("cp.async.wait_group 0;\n" ::: "memory");
        else              asm volatile("cp.async.wait_group 1;\n" ::: "memory");
        __syncthreads();
        if (c + 2 < NCH) issue(c + 2, (c + 2) % 3);
        if (tid < FB_NCOMP) {
            const float2* sp = ring + (c % 3) * FB_SLOTF2 + tid * FB_IPAD;
            #pragma unroll
            for (int i = 0; i < 8; ++i) {
                float2 fm = sp[i];
                float ft = fm.x, mt = fm.y;
                float Pc = fmaxf(0.01f, P), Zc = fmaxf(0.01f, Z);
                float gN = N / (chiC + N);
                float zg = rho2 * (1.0f - __expf(-lam005 * Pc)) * Zc;
                float up = gN * ft * Pc;
                float Nn = N + DT*(-up + alp03*zg + eps01*P + gam01*Z + phi04*D + mt*(8.0f - N));
                float Pn = P + DT*(up - zg - eps01*P - eta015*P - mt*P);
                float Zn = Z + DT*(bet06*zg - gam01*Z - mt*Z);
                float Dn = D + DT*(eta015*P + rem*zg - phi04*D - zet01*D - mt*D);
                N = Nn; P = Pn; Z = Zn; D = Dn;
            }
            o[0][c+1]=N; o[1][c+1]=P; o[2][c+1]=Z; o[3][c+1]=D;
        }
    }
    __syncthreads();
    float* obuf = (float*)ring;
    if (tid < FB_NCOMP) {
        float* ob = obuf + tid * 33;
        #pragma unroll
        for (int cc = 0; cc < 4; ++cc)
            #pragma unroll
            for (int k = 0; k < 8; ++k) ob[cc*8 + k] = o[cc][k];
    }
    __syncthreads();
    float* outb = out + (size_t)blockIdx.x * (FB_NCOMP * 32);
    #pragma unroll
    for (int i = tid; i < FB_NCOMP * 32; i += FB_NT)
        outb[i] = obuf[(i >> 5) * 33 + (i & 31)];
}

typedef CUresult (*EncodeFn)(
    CUtensorMap*, CUtensorMapDataType, cuuint32_t, void*,
    const cuuint64_t*, const cuuint64_t*, const cuuint32_t*, const cuuint32_t*,
    CUtensorMapInterleave, CUtensorMapSwizzle, CUtensorMapL2promotion,
    CUtensorMapFloatOOBfill);

extern "C" void kernel_launch(void* const* d_in, const int* in_sizes, int n_in,
                              void* d_out, int out_size)
{
    (void)in_sizes; (void)n_in; (void)out_size;
    const float* X_in = (const float*)d_in[0];
    void*        gf   = (void*)d_in[1];
    void*        gm   = (void*)d_in[2];
    const float* pvv  = (const float*)d_in[3];
    float* out        = (float*)d_out;

    bool tma_ok = false;
    static CUtensorMap tmf, tmm;

    void* h = dlopen("libcuda.so.1", RTLD_NOW | RTLD_GLOBAL);
    if (!h) h = dlopen("libcuda.so", RTLD_NOW | RTLD_GLOBAL);
    EncodeFn enc = h ? (EncodeFn)dlsym(h, "cuTensorMapEncodeTiled") : nullptr;

    if (enc) {
        cuuint64_t dims[3]    = {168, NWK, NB};
        cuuint64_t strides[2] = {168 * 4, (cuuint64_t)NHRS * 4};
        cuuint32_t box[3]     = {24, NWK, G};
        cuuint32_t estr[3]    = {1, 1, 1};
        CUresult r1 = enc(&tmf, CU_TENSOR_MAP_DATA_TYPE_FLOAT32, 3, gf,
                          dims, strides, box, estr,
                          CU_TENSOR_MAP_INTERLEAVE_NONE, CU_TENSOR_MAP_SWIZZLE_NONE,
                          CU_TENSOR_MAP_L2_PROMOTION_L2_128B,
                          CU_TENSOR_MAP_FLOAT_OOB_FILL_NONE);
        CUresult r2 = enc(&tmm, CU_TENSOR_MAP_DATA_TYPE_FLOAT32, 3, gm,
                          dims, strides, box, estr,
                          CU_TENSOR_MAP_INTERLEAVE_NONE, CU_TENSOR_MAP_SWIZZLE_NONE,
                          CU_TENSOR_MAP_L2_PROMOTION_L2_128B,
                          CU_TENSOR_MAP_FLOAT_OOB_FILL_NONE);
        tma_ok = (r1 == CUDA_SUCCESS && r2 == CUDA_SUCCESS);
    }

    if (tma_ok) {
        cudaFuncSetAttribute(npzd_tma,
                             cudaFuncAttributeMaxDynamicSharedMemorySize,
                             SMEM_BYTES);
        npzd_tma<<<GRID, NT, SMEM_BYTES>>>(tmf, tmm, X_in, pvv, out);
    } else {
        cudaFuncSetAttribute(npzd_fb,
                             cudaFuncAttributeMaxDynamicSharedMemorySize,
                             FB_SMEM);
        npzd_fb<<<NB / FB_G, FB_NT, FB_SMEM>>>(
            X_in, (const float*)gf, (const float*)gm, pvv, out);
    }
}

// round 16
// speedup vs baseline: 1.4286x; 1.0459x over previous
#include <cuda_runtime.h>
#include <cuda.h>
#include <cstdint>
#include <dlfcn.h>

// Model_NPZD_68401649156380 — R16: TMA tiles + 7 pipelines/SM + LDS.128 reads.
// gf/gm viewed as (2048, 52, 168) row-major. Block = 1 batch, NT=64.
// Per chunk c (8 steps): ONE cp.async.bulk.tensor.3d per array, box
// (24 @ x=24c, 52, 1), 3-slot mbarrier ring, depth-2 prefetch.
// Compute reads the 24-float span via 6x LDS.128 and extracts cols 3i
// from registers (x,w | z | y | x,w | z | y pattern).

#define NB      2048
#define NWK     52
#define NHRS    8760
#define DT      0.125f
#define NT      64
#define NCH     7
#define NSLOT   3
#define TILEF   (NWK * 24)              // 1248 floats per array per chunk
#define TILEB   (TILEF * 4)             // 4992 B (multiple of 128)
#define SLOTF   (2 * TILEF)             // f then m
#define SLOTB   (2 * TILEB)             // 9984 B
#define SMEM_BYTES (NSLOT * SLOTB + 128)   // 30080 B (incl. align slack)
#define GRID    NB                      // 2048

__device__ __forceinline__ void mbar_wait(uint32_t mb, uint32_t parity)
{
    uint32_t done;
    asm volatile(
        "{\n\t.reg .pred p;\n\t"
        "mbarrier.try_wait.parity.acquire.cta.shared::cta.b64 p, [%1], %2;\n\t"
        "selp.b32 %0, 1, 0, p;\n\t}"
        : "=r"(done) : "r"(mb), "r"(parity) : "memory");
    if (!done) {
        asm volatile(
            "{\n\t.reg .pred P1;\n\t"
            "W_%=:\n\t"
            "mbarrier.try_wait.parity.acquire.cta.shared::cta.b64 P1, [%0], %1, 0x989680;\n\t"
            "@P1 bra.uni D_%=;\n\t"
            "bra.uni W_%=;\n\t"
            "D_%=:\n\t}"
            :: "r"(mb), "r"(parity) : "memory");
    }
}

__global__ __launch_bounds__(NT) void npzd_tma(
    const __grid_constant__ CUtensorMap tmf,
    const __grid_constant__ CUtensorMap tmm,
    const float* __restrict__ X_in,
    const float* __restrict__ pv,
    float* __restrict__ out)
{
    extern __shared__ float rraw[];
    __shared__ __align__(8) unsigned long long mbar[NSLOT];

    const int tid = threadIdx.x;
    const int b   = blockIdx.x;

    // 128B-align the ring base (TMA smem destination requirement).
    uint32_t raw_sh = (uint32_t)__cvta_generic_to_shared(rraw);
    uint32_t rbase  = (raw_sh + 127u) & ~127u;
    float*   ringp  = (float*)((char*)rraw + (rbase - raw_sh));

    const uint32_t mbsh = (uint32_t)__cvta_generic_to_shared(mbar);
    const CUtensorMap* mf = &tmf;
    const CUtensorMap* mm = &tmm;

    if (tid == 0) {
        #pragma unroll
        for (int s = 0; s < NSLOT; ++s)
            asm volatile("mbarrier.init.shared.b64 [%0], 1;"
                         :: "r"(mbsh + s * 8) : "memory");
        asm volatile("fence.proxy.async.shared::cta;" ::: "memory");
    }
    __syncthreads();

    auto issue = [&](int c) {
        const int s = c % NSLOT;
        const uint32_t mb = mbsh + s * 8;
        const uint32_t df = rbase + (uint32_t)(s * SLOTB);
        const uint32_t dm = df + TILEB;
        asm volatile("mbarrier.arrive.expect_tx.shared.b64 _, [%0], %1;"
                     :: "r"(mb), "r"((uint32_t)SLOTB) : "memory");
        asm volatile(
            "cp.async.bulk.tensor.3d.shared::cta.global.tile.mbarrier::complete_tx::bytes"
            " [%0], [%1, {%2, %3, %4}], [%5];"
            :: "r"(df), "l"(mf), "r"(24 * c), "r"(0), "r"(b), "r"(mb) : "memory");
        asm volatile(
            "cp.async.bulk.tensor.3d.shared::cta.global.tile.mbarrier::complete_tx::bytes"
            " [%0], [%1, {%2, %3, %4}], [%5];"
            :: "r"(dm), "l"(mm), "r"(24 * c), "r"(0), "r"(b), "r"(mb) : "memory");
    };

    if (tid == 0) { issue(0); issue(1); }

    // ---- params + initial state (overlaps first TMA flights) ----
    const int w = tid;                  // valid for tid < NWK

    float chiC=0, rho2=0, gam01=0, lam005=0, eps01=0,
          alp03=0, bet06=0, eta015=0, phi04=0, zet01=0, rem=0;
    float N=0, P=0, Z=0, D=0;
    if (tid < NWK) {
        const float* p = pv + b * 10;
        chiC   = p[0];
        rho2   = p[1] * 2.0f;
        gam01  = p[2] * 0.1f;
        lam005 = p[3] * 0.05f;
        eps01  = p[4] * 0.1f;
        alp03  = p[5] * 0.3f;
        bet06  = p[6] * 0.6f;
        eta015 = p[7] * 0.15f;
        phi04  = p[8] * 0.4f;
        zet01  = p[9] * 0.1f;
        rem    = 1.0f - alp03 - bet06;

        const float* xi = X_in + ((size_t)(b * NWK + w)) * 5;
        N = xi[1]; P = xi[2]; Z = xi[3]; D = xi[4];
    }

    float o[4][8];
    o[0][0] = N; o[1][0] = P; o[2][0] = Z; o[3][0] = D;

    #pragma unroll 1
    for (int c = 0; c < NCH; ++c) {
        const int s = c % NSLOT;
        mbar_wait(mbsh + s * 8, (uint32_t)((c / NSLOT) & 1));

        if (tid < NWK) {
            // 6x LDS.128 per array; extract cols 3i from registers.
            const float4* f4 = (const float4*)(ringp + s * SLOTF + w * 24);
            const float4* m4 = (const float4*)(ringp + s * SLOTF + TILEF + w * 24);
            float4 a0 = f4[0], a1 = f4[1], a2 = f4[2],
                   a3 = f4[3], a4 = f4[4], a5 = f4[5];
            float4 c0 = m4[0], c1 = m4[1], c2 = m4[2],
                   c3 = m4[3], c4 = m4[4], c5 = m4[5];
            float fv[8] = {a0.x, a0.w, a1.z, a2.y, a3.x, a3.w, a4.z, a5.y};
            float mv[8] = {c0.x, c0.w, c1.z, c2.y, c3.x, c3.w, c4.z, c5.y};

            #pragma unroll
            for (int i = 0; i < 8; ++i) {
                float ft = fv[i], mt = mv[i];

                float Pc = fmaxf(0.01f, P);
                float Zc = fmaxf(0.01f, Z);
                float gN = N / (chiC + N);
                float zg = rho2 * (1.0f - __expf(-lam005 * Pc)) * Zc;
                float up = gN * ft * Pc;                    // Vm = 1

                float Nn = N + DT * (-up + alp03 * zg + eps01 * P + gam01 * Z
                                     + phi04 * D + mt * (8.0f - N));   // Q0=8
                float Pn = P + DT * (up - zg - eps01 * P - eta015 * P - mt * P);
                float Zn = Z + DT * (bet06 * zg - gam01 * Z - mt * Z);
                float Dn = D + DT * (eta015 * P + rem * zg - phi04 * D
                                     - zet01 * D - mt * D);
                N = Nn; P = Pn; Z = Zn; D = Dn;
            }
            o[0][c + 1] = N; o[1][c + 1] = P; o[2][c + 1] = Z; o[3][c + 1] = D;
        }
        __syncthreads();    // slot (c+2)%3's previous contents fully consumed

        if (tid == 0 && c + 2 < NCH)
            issue(c + 2);
    }
    __syncthreads();   // ring reads done; reuse smem for output transpose

    float* obuf = ringp;                 // 52*33 = 1716 floats, fits
    if (tid < NWK) {
        float* ob = obuf + tid * 33;
        #pragma unroll
        for (int cc = 0; cc < 4; ++cc)
            #pragma unroll
            for (int k = 0; k < 8; ++k)
                ob[cc * 8 + k] = o[cc][k];
    }
    __syncthreads();

    float* outb = out + (size_t)b * (NWK * 32);
    #pragma unroll
    for (int i = tid; i < NWK * 32; i += NT) {
        int t2 = i >> 5;
        int m  = i & 31;
        outb[i] = obuf[t2 * 33 + m];
    }
}

// ======================= Fallback: proven R10 pipeline =======================
#define FB_NT    256
#define FB_G     4
#define FB_NCOMP (FB_G * NWK)
#define FB_IPAD  9
#define FB_SLOTF2 (FB_NCOMP * FB_IPAD)
#define FB_SLOTB  (FB_SLOTF2 * 8)
#define FB_SMEM   (3 * FB_SLOTB)
#define FB_CHE    (FB_NCOMP * 8)
#define FB_KMAX   7

__global__ __launch_bounds__(FB_NT, 4) void npzd_fb(
    const float* __restrict__ X_in, const float* __restrict__ gf,
    const float* __restrict__ gm, const float* __restrict__ pv,
    float* __restrict__ out)
{
    extern __shared__ float2 ring[];
    const int tid = threadIdx.x;
    const int b0  = blockIdx.x * FB_G;
    const uint32_t ringsh = (uint32_t)__cvta_generic_to_shared(ring);

    int      srcOff[FB_KMAX];
    uint32_t dstRel[FB_KMAX];
    #pragma unroll
    for (int k = 0; k < FB_KMAX; ++k) {
        int e = tid + FB_NT * k;
        if (e < FB_CHE) {
            int gw = e >> 3, i = e & 7;
            int g = gw / NWK, w = gw - g * NWK;
            srcOff[k] = (b0 + g) * NHRS + 168 * w + 3 * i;
            dstRel[k] = (uint32_t)((gw * FB_IPAD + i) * 8);
        } else { srcOff[k] = 0; dstRel[k] = 0; }
    }
    auto issue = [&](int c, int slot) {
        const uint32_t sb = ringsh + (uint32_t)(slot * FB_SLOTB);
        const int add = 24 * c;
        #pragma unroll
        for (int k = 0; k < FB_KMAX; ++k) {
            if (k == FB_KMAX - 1 && tid >= (FB_CHE - FB_NT * (FB_KMAX - 1))) break;
            uint32_t d = sb + dstRel[k];
            asm volatile("cp.async.ca.shared.global [%0], [%1], 4;\n"
                         :: "r"(d), "l"(gf + (srcOff[k] + add)) : "memory");
            asm volatile("cp.async.ca.shared.global [%0], [%1], 4;\n"
                         :: "r"(d + 4), "l"(gm + (srcOff[k] + add)) : "memory");
        }
        asm volatile("cp.async.commit_group;\n" ::: "memory");
    };
    issue(0, 0); issue(1, 1);

    const int g = tid / NWK, w = tid - g * NWK, b = b0 + g;
    float chiC=0, rho2=0, gam01=0, lam005=0, eps01=0,
          alp03=0, bet06=0, eta015=0, phi04=0, zet01=0, rem=0;
    float N=0, P=0, Z=0, D=0;
    if (tid < FB_NCOMP) {
        const float* p = pv + b * 10;
        chiC = p[0]; rho2 = p[1]*2.0f; gam01 = p[2]*0.1f; lam005 = p[3]*0.05f;
        eps01 = p[4]*0.1f; alp03 = p[5]*0.3f; bet06 = p[6]*0.6f;
        eta015 = p[7]*0.15f; phi04 = p[8]*0.4f; zet01 = p[9]*0.1f;
        rem = 1.0f - alp03 - bet06;
        const float* xi = X_in + ((size_t)(b * NWK + w)) * 5;
        N = xi[1]; P = xi[2]; Z = xi[3]; D = xi[4];
    }
    float o[4][8];
    o[0][0]=N; o[1][0]=P; o[2][0]=Z; o[3][0]=D;
    #pragma unroll 1
    for (int c = 0; c < NCH; ++c) {
        if (c == NCH - 1) asm volatile("cp.async.wait_group 0;\n" ::: "memory");
        else              asm volatile("cp.async.wait_group 1;\n" ::: "memory");
        __syncthreads();
        if (c + 2 < NCH) issue(c + 2, (c + 2) % 3);
        if (tid < FB_NCOMP) {
            const float2* sp = ring + (c % 3) * FB_SLOTF2 + tid * FB_IPAD;
            #pragma unroll
            for (int i = 0; i < 8; ++i) {
                float2 fm = sp[i];
                float ft = fm.x, mt = fm.y;
                float Pc = fmaxf(0.01f, P), Zc = fmaxf(0.01f, Z);
                float gN = N / (chiC + N);
                float zg = rho2 * (1.0f - __expf(-lam005 * Pc)) * Zc;
                float up = gN * ft * Pc;
                float Nn = N + DT*(-up + alp03*zg + eps01*P + gam01*Z + phi04*D + mt*(8.0f - N));
                float Pn = P + DT*(up - zg - eps01*P - eta015*P - mt*P);
                float Zn = Z + DT*(bet06*zg - gam01*Z - mt*Z);
                float Dn = D + DT*(eta015*P + rem*zg - phi04*D - zet01*D - mt*D);
                N = Nn; P = Pn; Z = Zn; D = Dn;
            }
            o[0][c+1]=N; o[1][c+1]=P; o[2][c+1]=Z; o[3][c+1]=D;
        }
    }
    __syncthreads();
    float* obuf = (float*)ring;
    if (tid < FB_NCOMP) {
        float* ob = obuf + tid * 33;
        #pragma unroll
        for (int cc = 0; cc < 4; ++cc)
            #pragma unroll
            for (int k = 0; k < 8; ++k) ob[cc*8 + k] = o[cc][k];
    }
    __syncthreads();
    float* outb = out + (size_t)blockIdx.x * (FB_NCOMP * 32);
    #pragma unroll
    for (int i = tid; i < FB_NCOMP * 32; i += FB_NT)
        outb[i] = obuf[(i >> 5) * 33 + (i & 31)];
}

typedef CUresult (*EncodeFn)(
    CUtensorMap*, CUtensorMapDataType, cuuint32_t, void*,
    const cuuint64_t*, const cuuint64_t*, const cuuint32_t*, const cuuint32_t*,
    CUtensorMapInterleave, CUtensorMapSwizzle, CUtensorMapL2promotion,
    CUtensorMapFloatOOBfill);

extern "C" void kernel_launch(void* const* d_in, const int* in_sizes, int n_in,
                              void* d_out, int out_size)
{
    (void)in_sizes; (void)n_in; (void)out_size;
    const float* X_in = (const float*)d_in[0];
    void*        gf   = (void*)d_in[1];
    void*        gm   = (void*)d_in[2];
    const float* pvv  = (const float*)d_in[3];
    float* out        = (float*)d_out;

    bool tma_ok = false;
    static CUtensorMap tmf, tmm;

    void* h = dlopen("libcuda.so.1", RTLD_NOW | RTLD_GLOBAL);
    if (!h) h = dlopen("libcuda.so", RTLD_NOW | RTLD_GLOBAL);
    EncodeFn enc = h ? (EncodeFn)dlsym(h, "cuTensorMapEncodeTiled") : nullptr;

    if (enc) {
        cuuint64_t dims[3]    = {168, NWK, NB};
        cuuint64_t strides[2] = {168 * 4, (cuuint64_t)NHRS * 4};
        cuuint32_t box[3]     = {24, NWK, 1};
        cuuint32_t estr[3]    = {1, 1, 1};
        CUresult r1 = enc(&tmf, CU_TENSOR_MAP_DATA_TYPE_FLOAT32, 3, gf,
                          dims, strides, box, estr,
                          CU_TENSOR_MAP_INTERLEAVE_NONE, CU_TENSOR_MAP_SWIZZLE_NONE,
                          CU_TENSOR_MAP_L2_PROMOTION_L2_128B,
                          CU_TENSOR_MAP_FLOAT_OOB_FILL_NONE);
        CUresult r2 = enc(&tmm, CU_TENSOR_MAP_DATA_TYPE_FLOAT32, 3, gm,
                          dims, strides, box, estr,
                          CU_TENSOR_MAP_INTERLEAVE_NONE, CU_TENSOR_MAP_SWIZZLE_NONE,
                          CU_TENSOR_MAP_L2_PROMOTION_L2_128B,
                          CU_TENSOR_MAP_FLOAT_OOB_FILL_NONE);
        tma_ok = (r1 == CUDA_SUCCESS && r2 == CUDA_SUCCESS);
    }

    if (tma_ok) {
        cudaFuncSetAttribute(npzd_tma,
                             cudaFuncAttributeMaxDynamicSharedMemorySize,
                             SMEM_BYTES);
        npzd_tma<<<GRID, NT, SMEM_BYTES>>>(tmf, tmm, X_in, pvv, out);
    } else {
        cudaFuncSetAttribute(npzd_fb,
                             cudaFuncAttributeMaxDynamicSharedMemorySize,
                             FB_SMEM);
        npzd_fb<<<NB / FB_G, FB_NT, FB_SMEM>>>(
            X_in, (const float*)gf, (const float*)gm, pvv, out);
    }
}